// round 15
// baseline (speedup 1.0000x reference)
#include <cuda_runtime.h>
#include <cuda_bf16.h>
#include <cstdint>

// Problem constants (fixed shapes from reference setup_inputs)
#define BB 4
#define NN 8192
#define MM 4096
#define FF 64
#define KK 16
#define BM (BB * MM)        // 16384 queries total

// Scan configuration: R queries per warp, 8 warps per block, 4 points per lane/iter
#define R 2
#define WARPS 8
#define TPB (WARPS * 32)        // 256
#define QPB (WARPS * R)         // 16 queries per block
#define TILE 2048               // points per smem tile (32 KB packed)
#define GRP 128                 // points per inner iteration (4 per lane)

#define MIN_SIGMA_C 0.0001f
#define FLTMAX 3.402823466e+38f

// -------- static device scratch (no allocations allowed) --------
__device__ float g_featT[(size_t)BB * NN * FF];   // transposed features (B, N, F)

// -------- packed f32x2 helpers (sm_103a FFMA2; bit-exact vs scalar FFMA) --------
__device__ __forceinline__ uint64_t pk2(float lo, float hi) {
    uint64_t r; asm("mov.b64 %0,{%1,%2};" : "=l"(r) : "f"(lo), "f"(hi)); return r;
}
__device__ __forceinline__ void upk2(uint64_t v, float& lo, float& hi) {
    asm("mov.b64 {%0,%1},%2;" : "=f"(lo), "=f"(hi) : "l"(v));
}
__device__ __forceinline__ uint64_t fma2(uint64_t a, uint64_t b, uint64_t c) {
    uint64_t d; asm("fma.rn.f32x2 %0,%1,%2,%3;" : "=l"(d) : "l"(a), "l"(b), "l"(c)); return d;
}
__device__ __forceinline__ void lds2x64(uint32_t addr, uint64_t& a, uint64_t& b) {
    asm("ld.shared.v2.b64 {%0,%1},[%2];" : "=l"(a), "=l"(b) : "r"(addr));
}

// ================= Kernel 1: feature transpose (B,F,N) -> (B,N,F) =================
__global__ void transpose_kernel(const float* __restrict__ feat) {
    __shared__ float tile[32][33];
    int b  = blockIdx.z;
    int f0 = blockIdx.y * 32;
    int n0 = blockIdx.x * 32;
    int tx = threadIdx.x, ty = threadIdx.y;   // block (32, 8)
#pragma unroll
    for (int i = ty; i < 32; i += 8)
        tile[i][tx] = feat[((size_t)b * FF + (f0 + i)) * NN + n0 + tx];
    __syncthreads();
#pragma unroll
    for (int i = ty; i < 32; i += 8)
        g_featT[((size_t)b * NN + (n0 + i)) * FF + f0 + tx] = tile[tx][i];
}

// ================= Kernel 2: fused top-16 + softmax + outputs =====================
// grid: (MM/QPB, BB) = 1024 blocks, block 256, 6 blocks/SM.
// Sorted ascending list per query distributed across lanes 0..15 (lane l = slot l).
// score = |p|^2 - 2 q.p  (monotone in d2 for fixed q -> valid for selection)
// Tile layout: pair j = points (2j, 2j+1); xy[j]=(x0,x1,y0,y1), zw[j]=(z0,z1,w0,w1).
__global__ __launch_bounds__(TPB, 6)
void fused_kernel(const float* __restrict__ pc, const float* __restrict__ qc,
                  const float* __restrict__ temp, float* __restrict__ out) {
    __shared__ union SU {
        struct { float4 xy[TILE / 2]; float4 zw[TILE / 2]; } pk;   // 32 KB, scan phase
        struct {
            float sfeat[QPB][FF + 2];               // padded staging
            float spp[QPB][4];
        } ep;                                       // ~4.5 KB, epilogue phase
    } sm;

    const int tid  = threadIdx.x;
    const int lane = tid & 31;
    const int w    = tid >> 5;
    const int b    = blockIdx.y;
    const int m0   = blockIdx.x * QPB;
    const int mw   = m0 + w * R;                    // warp's first query

    const float* pcb = pc + (size_t)b * 3 * NN;
    const float* qcb = qc + (size_t)b * 3 * MM;

    uint64_t qxp[R], qyp[R], qzp[R];                // (-2q, -2q) packed, both halves equal
#pragma unroll
    for (int r = 0; r < R; ++r) {
        float x = -2.0f * qcb[mw + r];
        float y = -2.0f * qcb[MM + mw + r];
        float z = -2.0f * qcb[2 * MM + mw + r];
        qxp[r] = pk2(x, x); qyp[r] = pk2(y, y); qzp[r] = pk2(z, z);
    }

    float vs[R]; int vix[R]; float thr[R];
#pragma unroll
    for (int r = 0; r < R; ++r) { vs[r] = FLTMAX; vix[r] = 0; thr[r] = FLTMAX; }

    // fast insert: no recheck, no per-candidate thr update. No-op if v doesn't qualify.
#define FAST_INSERT(rr, v, vi)                                          \
    do {                                                                \
        float prev = __shfl_up_sync(0xffffffffu, vs[rr], 1);            \
        int  previ = __shfl_up_sync(0xffffffffu, vix[rr], 1);           \
        if (lane == 0) prev = -FLTMAX;                                  \
        bool cprev = (v) < prev;                                        \
        bool cm    = (v) < vs[rr];                                      \
        vix[rr] = cprev ? previ : (cm ? (vi) : vix[rr]);                \
        vs[rr]  = fminf(fmaxf((v), prev), vs[rr]);                      \
    } while (0)

    const uint32_t sb_xy = (uint32_t)__cvta_generic_to_shared(sm.pk.xy);
    const uint32_t sb_zw = (uint32_t)__cvta_generic_to_shared(sm.pk.zw);

    for (int tile = 0; tile < NN / TILE; ++tile) {
        const int n0 = tile * TILE;
        __syncthreads();
        {   // fill pair-packed tile (pair j = points n0+2j, n0+2j+1)
            const float2* px2 = (const float2*)(pcb + n0);
            const float2* py2 = (const float2*)(pcb + NN + n0);
            const float2* pz2 = (const float2*)(pcb + 2 * NN + n0);
            for (int j = tid; j < TILE / 2; j += TPB) {
                float2 x = px2[j], y = py2[j], z = pz2[j];
                float w0 = fmaf(x.x, x.x, fmaf(y.x, y.x, z.x * z.x));
                float w1 = fmaf(x.y, x.y, fmaf(y.y, y.y, z.y * z.y));
                sm.pk.xy[j] = make_float4(x.x, x.y, y.x, y.y);
                sm.pk.zw[j] = make_float4(z.x, z.y, w0, w1);
            }
        }
        __syncthreads();

        int i0 = 0;
        if (tile == 0) {
            // ---- peeled first group (128 pts): thr wide open -> tightening inserts ----
            const uint32_t oa = lane * 16, ob = (32 + lane) * 16;
            uint64_t xa, ya, za, wa, xb, yb, zb, wb;
            lds2x64(sb_xy + oa, xa, ya); lds2x64(sb_zw + oa, za, wa);
            lds2x64(sb_xy + ob, xb, yb); lds2x64(sb_zw + ob, zb, wb);
#pragma unroll
            for (int r = 0; r < R; ++r) {
                uint64_t s2a = fma2(xa, qxp[r], fma2(ya, qyp[r], fma2(za, qzp[r], wa)));
                uint64_t s2b = fma2(xb, qxp[r], fma2(yb, qyp[r], fma2(zb, qzp[r], wb)));
                float a0, a1, b0, b1;
                upk2(s2a, a0, a1); upk2(s2b, b0, b1);
                unsigned ea = __ballot_sync(0xffffffffu, a0 < thr[r]);
                unsigned oaM = __ballot_sync(0xffffffffu, a1 < thr[r]);
                unsigned eb = __ballot_sync(0xffffffffu, b0 < thr[r]);
                unsigned obM = __ballot_sync(0xffffffffu, b1 < thr[r]);
                unsigned m = ea | oaM;
                while (m) {                         // ascending index, with recheck
                    int src = __ffs(m) - 1; m &= m - 1;
                    float vlo = __shfl_sync(0xffffffffu, a0, src);
                    float vhi = __shfl_sync(0xffffffffu, a1, src);
                    if (((ea >> src) & 1) && vlo < thr[r]) {
                        FAST_INSERT(r, vlo, 2 * src);
                        thr[r] = __shfl_sync(0xffffffffu, vs[r], 15);
                    }
                    if (((oaM >> src) & 1) && vhi < thr[r]) {
                        FAST_INSERT(r, vhi, 2 * src + 1);
                        thr[r] = __shfl_sync(0xffffffffu, vs[r], 15);
                    }
                }
                m = eb | obM;
                while (m) {
                    int src = __ffs(m) - 1; m &= m - 1;
                    float vlo = __shfl_sync(0xffffffffu, b0, src);
                    float vhi = __shfl_sync(0xffffffffu, b1, src);
                    if (((eb >> src) & 1) && vlo < thr[r]) {
                        FAST_INSERT(r, vlo, 64 + 2 * src);
                        thr[r] = __shfl_sync(0xffffffffu, vs[r], 15);
                    }
                    if (((obM >> src) & 1) && vhi < thr[r]) {
                        FAST_INSERT(r, vhi, 64 + 2 * src + 1);
                        thr[r] = __shfl_sync(0xffffffffu, vs[r], 15);
                    }
                }
            }
            i0 = 1;
        }

#pragma unroll 2
        for (int i = i0; i < TILE / GRP; ++i) {
            const uint32_t oa = (i * 64 + lane) * 16, ob = (i * 64 + 32 + lane) * 16;
            uint64_t xa, ya, za, wa, xb, yb, zb, wb;
            lds2x64(sb_xy + oa, xa, ya); lds2x64(sb_zw + oa, za, wa);
            lds2x64(sb_xy + ob, xb, yb); lds2x64(sb_zw + ob, zb, wb);
#pragma unroll
            for (int r = 0; r < R; ++r) {
                uint64_t s2a = fma2(xa, qxp[r], fma2(ya, qyp[r], fma2(za, qzp[r], wa)));
                uint64_t s2b = fma2(xb, qxp[r], fma2(yb, qyp[r], fma2(zb, qzp[r], wb)));
                float a0, a1, b0, b1;
                upk2(s2a, a0, a1); upk2(s2b, b0, b1);
                float mn = fminf(fminf(a0, a1), fminf(b0, b1));
                if (__ballot_sync(0xffffffffu, mn < thr[r])) {      // rare
                    const int base = n0 + i * GRP;
                    unsigned ea  = __ballot_sync(0xffffffffu, a0 < thr[r]);
                    unsigned oaM = __ballot_sync(0xffffffffu, a1 < thr[r]);
                    unsigned eb  = __ballot_sync(0xffffffffu, b0 < thr[r]);
                    unsigned obM = __ballot_sync(0xffffffffu, b1 < thr[r]);
                    unsigned m = ea | oaM;
                    while (m) {                     // ascending index order
                        int src = __ffs(m) - 1; m &= m - 1;
                        float vlo = __shfl_sync(0xffffffffu, a0, src);
                        float vhi = __shfl_sync(0xffffffffu, a1, src);
                        if ((ea  >> src) & 1) FAST_INSERT(r, vlo, base + 2 * src);
                        if ((oaM >> src) & 1) FAST_INSERT(r, vhi, base + 2 * src + 1);
                    }
                    m = eb | obM;
                    while (m) {
                        int src = __ffs(m) - 1; m &= m - 1;
                        float vlo = __shfl_sync(0xffffffffu, b0, src);
                        float vhi = __shfl_sync(0xffffffffu, b1, src);
                        if ((eb  >> src) & 1) FAST_INSERT(r, vlo, base + 64 + 2 * src);
                        if ((obM >> src) & 1) FAST_INSERT(r, vhi, base + 64 + 2 * src + 1);
                    }
                    thr[r] = __shfl_sync(0xffffffffu, vs[r], 15);   // once per group
                }
            }
        }
    }

    // ================= fused epilogue =================
    __syncthreads();                                // done with tile; overlay as ep
    const float tv = __ldg(temp);
    const float inv_sigma = 1.0f / fmaxf(tv * tv, MIN_SIGMA_C);
    const float* fbase = g_featT + (size_t)b * NN * FF;

#pragma unroll
    for (int r = 0; r < R; ++r) {
        const int q  = w * R + r;                   // block-local query id
        const int n  = vix[r];
        float qxl, qxh, qyl, qyh, qzl, qzh;         // recover q from packs (halves equal)
        upk2(qxp[r], qxl, qxh); upk2(qyp[r], qyl, qyh); upk2(qzp[r], qzl, qzh);
        const float qx = -0.5f * qxl, qy = -0.5f * qyl, qz = -0.5f * qzl;

        const float px = pcb[n], py = pcb[NN + n], pz = pcb[2 * NN + n];
        const float dx = px - qx, dy = py - qy, dz = pz - qz;
        const float d2 = fmaf(dx, dx, fmaf(dy, dy, dz * dz));

        float d2m = (lane < KK) ? d2 : FLTMAX;      // warp-min over 16 real slots
#pragma unroll
        for (int o = 16; o >= 1; o >>= 1) d2m = fminf(d2m, __shfl_xor_sync(0xffffffffu, d2m, o));

        float wgt = (lane < KK) ? __expf((d2m - d2) * inv_sigma) : 0.0f;
        float wsum = wgt;
#pragma unroll
        for (int o = 16; o >= 1; o >>= 1) wsum += __shfl_xor_sync(0xffffffffu, wsum, o);
        wgt *= 1.0f / wsum;

        // projected point
        float sx = wgt * px, sy = wgt * py, sz = wgt * pz;
#pragma unroll
        for (int o = 16; o >= 1; o >>= 1) {
            sx += __shfl_xor_sync(0xffffffffu, sx, o);
            sy += __shfl_xor_sync(0xffffffffu, sy, o);
            sz += __shfl_xor_sync(0xffffffffu, sz, o);
        }
        if (lane == 0) { sm.ep.spp[q][0] = sx; sm.ep.spp[q][1] = sy; sm.ep.spp[q][2] = sz; }

        // features: per neighbor j broadcast (w_j, n_j); 32 lanes load float2 (256B row)
        float ax = 0.0f, ay = 0.0f;
#pragma unroll
        for (int j = 0; j < KK; ++j) {
            float wj = __shfl_sync(0xffffffffu, wgt, j);
            int   nj = __shfl_sync(0xffffffffu, vix[r], j);
            float2 v = *reinterpret_cast<const float2*>(fbase + (size_t)nj * FF + 2 * lane);
            ax = fmaf(wj, v.x, ax);
            ay = fmaf(wj, v.y, ay);
        }
        *reinterpret_cast<float2*>(&sm.ep.sfeat[q][2 * lane]) = make_float2(ax, ay);
    }
    __syncthreads();

    // ---- coalesced block-wide stores (16 consecutive m per segment) ----
    if (tid < 3 * QPB) {                            // projected (B,3,M)
        int d = tid >> 4, ql = tid & 15;
        out[((size_t)b * 3 + d) * MM + m0 + ql] = sm.ep.spp[ql][d];
    }
    float* outf = out + (size_t)BB * 3 * MM;        // propagated (B,F,M)
#pragma unroll
    for (int rr = 0; rr < (QPB * FF) / TPB; ++rr) {
        int idx = rr * TPB + tid;
        int f = idx >> 4, ql = idx & 15;
        outf[((size_t)b * FF + f) * MM + m0 + ql] = sm.ep.sfeat[ql][f];
    }
#undef FAST_INSERT
}

// ================= launch =================
extern "C" void kernel_launch(void* const* d_in, const int* in_sizes, int n_in,
                              void* d_out, int out_size) {
    const float* point_cloud    = (const float*)d_in[0];  // (B, 3, N)
    const float* query_cloud    = (const float*)d_in[1];  // (B, 3, M)
    const float* point_features = (const float*)d_in[2];  // (B, F, N)
    const float* temperature    = (const float*)d_in[3];  // scalar
    float* out = (float*)d_out;  // [projected (B,3,M) | propagated (B,F,M)]

    (void)in_sizes; (void)n_in; (void)out_size;

    dim3 tgrid(NN / 32, FF / 32, BB);
    dim3 tblk(32, 8);
    transpose_kernel<<<tgrid, tblk>>>(point_features);

    dim3 sgrid(MM / QPB, BB);
    fused_kernel<<<sgrid, TPB>>>(point_cloud, query_cloud, temperature, (float*)d_out);
}

// round 17
// speedup vs baseline: 1.2009x; 1.2009x over previous
#include <cuda_runtime.h>
#include <cuda_bf16.h>
#include <cstdint>

// Problem constants (fixed shapes from reference setup_inputs)
#define BB 4
#define NN 8192
#define MM 4096
#define FF 64
#define KK 16
#define BM (BB * MM)        // 16384 queries total

// Scan configuration: R queries per warp, 8 warps per block, 2 points per lane/iter
#define R 2
#define WARPS 8
#define TPB (WARPS * 32)        // 256
#define QPB (WARPS * R)         // 16 queries per block
#define TILE 2048               // points per smem tile (32 KB of float4)
#define GRP 64                  // points per inner iteration (2 per lane)

#define MIN_SIGMA_C 0.0001f
#define FLTMAX 3.402823466e+38f

// -------- static device scratch (no allocations allowed) --------
__device__ float g_featT[(size_t)BB * NN * FF];   // transposed features (B, N, F)

// ================= Kernel 1: feature transpose (B,F,N) -> (B,N,F) =================
__global__ void transpose_kernel(const float* __restrict__ feat) {
    __shared__ float tile[32][33];
    int b  = blockIdx.z;
    int f0 = blockIdx.y * 32;
    int n0 = blockIdx.x * 32;
    int tx = threadIdx.x, ty = threadIdx.y;   // block (32, 8)
#pragma unroll
    for (int i = ty; i < 32; i += 8)
        tile[i][tx] = feat[((size_t)b * FF + (f0 + i)) * NN + n0 + tx];
    __syncthreads();
#pragma unroll
    for (int i = ty; i < 32; i += 8)
        g_featT[((size_t)b * NN + (n0 + i)) * FF + f0 + tx] = tile[tx][i];
}

// ================= Kernel 2: fused top-16 + softmax + outputs =====================
// grid: (MM/QPB, BB), block 256, 6 blocks/SM. Warp w owns queries mw .. mw+R-1.
// Sorted ascending list per query distributed across lanes 0..15 (lane l = slot l).
// score = |p|^2 - 2 q.p  (monotone in d2 for fixed q -> valid for selection).
// Hot loop: ONE combined ballot per 64-pt group; precise per-query ballots only
// inside the rare hit path (DRAIN_R), insertion order A-half then B-half ascending.
__global__ __launch_bounds__(TPB, 6)
void fused_kernel(const float* __restrict__ pc, const float* __restrict__ qc,
                  const float* __restrict__ temp, float* __restrict__ out) {
    __shared__ union SU {
        float4 spts[TILE];                          // 32 KB, scan phase
        struct {
            float sfeat[QPB][FF + 2];               // padded staging
            float spp[QPB][4];
        } ep;                                       // ~4.5 KB, epilogue phase
    } sm;

    const int tid  = threadIdx.x;
    const int lane = tid & 31;
    const int w    = tid >> 5;
    const int b    = blockIdx.y;
    const int m0   = blockIdx.x * QPB;
    const int mw   = m0 + w * R;                    // warp's first query

    const float* pcb = pc + (size_t)b * 3 * NN;
    const float* qcb = qc + (size_t)b * 3 * MM;

    float qx2[R], qy2[R], qz2[R];
#pragma unroll
    for (int r = 0; r < R; ++r) {
        qx2[r] = -2.0f * qcb[mw + r];
        qy2[r] = -2.0f * qcb[MM + mw + r];
        qz2[r] = -2.0f * qcb[2 * MM + mw + r];
    }

    float vs[R]; int vix[R]; float thr[R];
#pragma unroll
    for (int r = 0; r < R; ++r) { vs[r] = FLTMAX; vix[r] = 0; thr[r] = FLTMAX; }

    // fast insert: no recheck, no per-candidate thr update. No-op if v doesn't qualify.
#define FAST_INSERT(rr, v, vi)                                          \
    do {                                                                \
        float prev = __shfl_up_sync(0xffffffffu, vs[rr], 1);            \
        int  previ = __shfl_up_sync(0xffffffffu, vix[rr], 1);           \
        if (lane == 0) prev = -FLTMAX;                                  \
        bool cprev = (v) < prev;                                        \
        bool cm    = (v) < vs[rr];                                      \
        vix[rr] = cprev ? previ : (cm ? (vi) : vix[rr]);                \
        vs[rr]  = fminf(fmaxf((v), prev), vs[rr]);                      \
    } while (0)

    // precise per-query drain for one 64-pt group (A-half then B-half, ascending idx)
#define DRAIN_R(rr, scA, scB, base)                                     \
    do {                                                                \
        unsigned bA = __ballot_sync(0xffffffffu, (scA) < thr[rr]);      \
        unsigned bB = __ballot_sync(0xffffffffu, (scB) < thr[rr]);      \
        if (bA | bB) {                                                  \
            while (bA) {                                                \
                int src = __ffs(bA) - 1;                                \
                bA &= bA - 1;                                           \
                float v = __shfl_sync(0xffffffffu, (scA), src);         \
                FAST_INSERT(rr, v, (base) + src);                       \
            }                                                           \
            while (bB) {                                                \
                int src = __ffs(bB) - 1;                                \
                bB &= bB - 1;                                           \
                float v = __shfl_sync(0xffffffffu, (scB), src);         \
                FAST_INSERT(rr, v, (base) + 32 + src);                  \
            }                                                           \
            thr[rr] = __shfl_sync(0xffffffffu, vs[rr], 15);             \
        }                                                               \
    } while (0)

    for (int tile = 0; tile < NN / TILE; ++tile) {
        const int n0 = tile * TILE;
        __syncthreads();
        for (int t = tid; t < TILE; t += TPB) {
            float x = pcb[n0 + t];
            float y = pcb[NN + n0 + t];
            float z = pcb[2 * NN + n0 + t];
            sm.spts[t] = make_float4(x, y, z, fmaf(x, x, fmaf(y, y, z * z)));
        }
        __syncthreads();

        int i0 = 0;
        if (tile == 0) {
            // ---- peeled first group: thr is wide open, use tightening inserts ----
            float4 pA = sm.spts[lane];
            float4 pB = sm.spts[32 + lane];
#pragma unroll
            for (int r = 0; r < R; ++r) {
#pragma unroll
                for (int ps = 0; ps < 2; ++ps) {
                    float4 p  = ps ? pB : pA;
                    int    nb = ps * 32;
                    float sc = fmaf(p.x, qx2[r], fmaf(p.y, qy2[r], fmaf(p.z, qz2[r], p.w)));
                    unsigned ball = __ballot_sync(0xffffffffu, sc < thr[r]);
                    while (ball) {
                        int src = __ffs(ball) - 1;
                        ball &= ball - 1;
                        float v = __shfl_sync(0xffffffffu, sc, src);
                        if (v < thr[r]) {
                            FAST_INSERT(r, v, nb + src);
                            thr[r] = __shfl_sync(0xffffffffu, vs[r], 15);
                        }
                    }
                }
            }
            i0 = 1;
        }

#pragma unroll 2
        for (int i = i0; i < TILE / GRP; ++i) {
            float4 pA = sm.spts[i * GRP + lane];        // one pair of LDS.128 serves R queries
            float4 pB = sm.spts[i * GRP + 32 + lane];
            float scA0 = fmaf(pA.x, qx2[0], fmaf(pA.y, qy2[0], fmaf(pA.z, qz2[0], pA.w)));
            float scB0 = fmaf(pB.x, qx2[0], fmaf(pB.y, qy2[0], fmaf(pB.z, qz2[0], pB.w)));
            float scA1 = fmaf(pA.x, qx2[1], fmaf(pA.y, qy2[1], fmaf(pA.z, qz2[1], pA.w)));
            float scB1 = fmaf(pB.x, qx2[1], fmaf(pB.y, qy2[1], fmaf(pB.z, qz2[1], pB.w)));
            float mn0 = fminf(scA0, scB0);
            float mn1 = fminf(scA1, scB1);
            bool c0 = mn0 < thr[0];
            bool c1 = mn1 < thr[1];
            if (__ballot_sync(0xffffffffu, c0 | c1)) {  // ONE hot ballot per group
                const int base = n0 + i * GRP;
                DRAIN_R(0, scA0, scB0, base);
                DRAIN_R(1, scA1, scB1, base);
            }
        }
    }

    // ================= fused epilogue =================
    __syncthreads();                                // done with spts; overlay as ep
    const float tv = __ldg(temp);
    const float inv_sigma = 1.0f / fmaxf(tv * tv, MIN_SIGMA_C);
    const float* fbase = g_featT + (size_t)b * NN * FF;

#pragma unroll
    for (int r = 0; r < R; ++r) {
        const int q  = w * R + r;                   // block-local query id
        const int n  = vix[r];
        const float qx = -0.5f * qx2[r];            // exact recovery
        const float qy = -0.5f * qy2[r];
        const float qz = -0.5f * qz2[r];

        const float px = pcb[n], py = pcb[NN + n], pz = pcb[2 * NN + n];
        const float dx = px - qx, dy = py - qy, dz = pz - qz;
        const float d2 = fmaf(dx, dx, fmaf(dy, dy, dz * dz));

        float d2m = (lane < KK) ? d2 : FLTMAX;      // warp-min over 16 real slots
#pragma unroll
        for (int o = 16; o >= 1; o >>= 1) d2m = fminf(d2m, __shfl_xor_sync(0xffffffffu, d2m, o));

        float wgt = (lane < KK) ? __expf((d2m - d2) * inv_sigma) : 0.0f;
        float wsum = wgt;
#pragma unroll
        for (int o = 16; o >= 1; o >>= 1) wsum += __shfl_xor_sync(0xffffffffu, wsum, o);
        wgt *= 1.0f / wsum;

        // projected point
        float sx = wgt * px, sy = wgt * py, sz = wgt * pz;
#pragma unroll
        for (int o = 16; o >= 1; o >>= 1) {
            sx += __shfl_xor_sync(0xffffffffu, sx, o);
            sy += __shfl_xor_sync(0xffffffffu, sy, o);
            sz += __shfl_xor_sync(0xffffffffu, sz, o);
        }
        if (lane == 0) { sm.ep.spp[q][0] = sx; sm.ep.spp[q][1] = sy; sm.ep.spp[q][2] = sz; }

        // features: per neighbor j broadcast (w_j, n_j); 32 lanes load float2 (256B row)
        float ax = 0.0f, ay = 0.0f;
#pragma unroll
        for (int j = 0; j < KK; ++j) {
            float wj = __shfl_sync(0xffffffffu, wgt, j);
            int   nj = __shfl_sync(0xffffffffu, vix[r], j);
            float2 v = *reinterpret_cast<const float2*>(fbase + (size_t)nj * FF + 2 * lane);
            ax = fmaf(wj, v.x, ax);
            ay = fmaf(wj, v.y, ay);
        }
        *reinterpret_cast<float2*>(&sm.ep.sfeat[q][2 * lane]) = make_float2(ax, ay);
    }
    __syncthreads();

    // ---- coalesced block-wide stores (16 consecutive m per segment) ----
    if (tid < 3 * QPB) {                            // projected (B,3,M)
        int d = tid >> 4, ql = tid & 15;
        out[((size_t)b * 3 + d) * MM + m0 + ql] = sm.ep.spp[ql][d];
    }
    float* outf = out + (size_t)BB * 3 * MM;        // propagated (B,F,M)
#pragma unroll
    for (int rr = 0; rr < (QPB * FF) / TPB; ++rr) {
        int idx = rr * TPB + tid;
        int f = idx >> 4, ql = idx & 15;
        outf[((size_t)b * FF + f) * MM + m0 + ql] = sm.ep.sfeat[ql][f];
    }
#undef DRAIN_R
#undef FAST_INSERT
}

// ================= launch =================
extern "C" void kernel_launch(void* const* d_in, const int* in_sizes, int n_in,
                              void* d_out, int out_size) {
    const float* point_cloud    = (const float*)d_in[0];  // (B, 3, N)
    const float* query_cloud    = (const float*)d_in[1];  // (B, 3, M)
    const float* point_features = (const float*)d_in[2];  // (B, F, N)
    const float* temperature    = (const float*)d_in[3];  // scalar
    float* out = (float*)d_out;  // [projected (B,3,M) | propagated (B,F,M)]

    (void)in_sizes; (void)n_in; (void)out_size;

    dim3 tgrid(NN / 32, FF / 32, BB);
    dim3 tblk(32, 8);
    transpose_kernel<<<tgrid, tblk>>>(point_features);

    dim3 sgrid(MM / QPB, BB);
    fused_kernel<<<sgrid, TPB>>>(point_cloud, query_cloud, temperature, (float*)d_out);
}